// round 1
// baseline (speedup 1.0000x reference)
#include <cuda_runtime.h>
#include <cstdint>

#define BATCH   16384
#define IN_F    512
#define OUT_F   64
#define LEAVES  256
#define GATES   255
#define PI_F    3.14159265358979323846f

// Scratch: sigmoid gate activations, stored transposed [gate][batch] for
// coalesced access in the leaf-probability kernel. 255*16384*4 = 16.7 MB.
__device__ float g_gates[GATES * BATCH];

// ---------------------------------------------------------------------------
// helpers
// ---------------------------------------------------------------------------
__device__ __forceinline__ float to_tf32(float x) {
    uint32_t u;
    asm("cvt.rna.tf32.f32 %0, %1;" : "=r"(u) : "f"(x));
    return __uint_as_float(u);
}

__device__ __forceinline__ float sigmoid_f(float z) {
    return __fdividef(1.0f, 1.0f + __expf(-z));
}

// tanh(z)*pi via exp; handles +/-inf saturation correctly.
__device__ __forceinline__ float tanhpi_f(float z) {
    float e = __expf(2.0f * z);
    return (1.0f - __fdividef(2.0f, e + 1.0f)) * PI_F;
}

__device__ __forceinline__ float activate(float v, int o) {
    return (o < 32) ? tanhpi_f(v) : sigmoid_f(v);
}

__device__ __forceinline__ void mma_tf32(float c[4], const uint32_t a[4],
                                         uint32_t b0, uint32_t b1) {
    asm volatile(
        "mma.sync.aligned.m16n8k8.row.col.f32.tf32.tf32.f32 "
        "{%0,%1,%2,%3}, {%4,%5,%6,%7}, {%8,%9}, {%0,%1,%2,%3};\n"
        : "+f"(c[0]), "+f"(c[1]), "+f"(c[2]), "+f"(c[3])
        : "r"(a[0]), "r"(a[1]), "r"(a[2]), "r"(a[3]), "r"(b0), "r"(b1));
}

// ---------------------------------------------------------------------------
// Kernel 1: gate GEMM  G = sigmoid(X @ GW + gb), full fp32 (precision-critical)
// Tile 64x64, BK=16, 256 threads, 4x4 micro-tile per thread.
// grid (4 n-blocks, 256 m-blocks)
// ---------------------------------------------------------------------------
__global__ __launch_bounds__(256) void gates_kernel(
    const float* __restrict__ x, const float* __restrict__ gw,
    const float* __restrict__ gb)
{
    __shared__ __align__(16) float As[16][68];   // [k][m]
    __shared__ __align__(16) float Bs[16][68];   // [k][n]

    const int tid = threadIdx.x;
    const int nb = blockIdx.x;   // 0..3
    const int mb = blockIdx.y;   // 0..255
    const int tx = tid & 15, ty = tid >> 4;

    float acc[4][4];
#pragma unroll
    for (int i = 0; i < 4; ++i)
#pragma unroll
        for (int j = 0; j < 4; ++j) acc[i][j] = 0.0f;

    const int xr = tid >> 2;          // 0..63
    const int xc = (tid & 3) * 4;     // 0,4,8,12
    const int wr = tid >> 4;          // 0..15
    const int wc = (tid & 15) * 4;    // 0..60

    for (int kt = 0; kt < IN_F; kt += 16) {
        __syncthreads();
        // X tile: 64 rows x 16 k
        float4 v = *reinterpret_cast<const float4*>(
            &x[(size_t)(mb * 64 + xr) * IN_F + kt + xc]);
        As[xc + 0][xr] = v.x; As[xc + 1][xr] = v.y;
        As[xc + 2][xr] = v.z; As[xc + 3][xr] = v.w;
        // GW tile: 16 k x 64 n (guarded: 255 cols)
#pragma unroll
        for (int j = 0; j < 4; ++j) {
            int n = nb * 64 + wc + j;
            Bs[wr][wc + j] = (n < GATES) ? gw[(size_t)(kt + wr) * GATES + n] : 0.0f;
        }
        __syncthreads();
#pragma unroll
        for (int k = 0; k < 16; ++k) {
            float a[4], b[4];
            *reinterpret_cast<float4*>(a) = *reinterpret_cast<float4*>(&As[k][ty * 4]);
            *reinterpret_cast<float4*>(b) = *reinterpret_cast<float4*>(&Bs[k][tx * 4]);
#pragma unroll
            for (int i = 0; i < 4; ++i)
#pragma unroll
                for (int j = 0; j < 4; ++j) acc[i][j] += a[i] * b[j];
        }
    }

#pragma unroll
    for (int j = 0; j < 4; ++j) {
        int n = nb * 64 + tx * 4 + j;
        if (n >= GATES) continue;
        float gbv = gb[n];
#pragma unroll
        for (int i = 0; i < 4; ++i) {
            int b = mb * 64 + ty * 4 + i;
            g_gates[(size_t)n * BATCH + b] = sigmoid_f(acc[i][j] + gbv);
        }
    }
}

// ---------------------------------------------------------------------------
// Kernel 2: leaf probabilities. One thread per batch row.
// Expand levels 0..4 into 32 register densities, then expand 3 more levels.
// Gate loads are coalesced ([gate][batch] layout, batch stride-1 across lanes).
// ---------------------------------------------------------------------------
__global__ __launch_bounds__(256) void leaf_kernel(float* __restrict__ lp)
{
    const int b = blockIdx.x * 256 + threadIdx.x;

    float dens[32];
    dens[0] = 1.0f;
#pragma unroll
    for (int d = 0; d < 5; ++d) {
        const int width = 1 << d;
        const int base = width - 1;
#pragma unroll
        for (int i = width - 1; i >= 0; --i) {
            float g = g_gates[(size_t)(base + i) * BATCH + b];
            float v = dens[i];
            float vg = v * g;
            dens[2 * i]     = vg;
            dens[2 * i + 1] = v - vg;
        }
    }
#pragma unroll
    for (int i = 0; i < 32; ++i) {
        float p  = dens[i];
        float g5 = g_gates[(size_t)(31 + i) * BATCH + b];
        float a0 = p * g5, a1 = p - a0;
        float g6a = g_gates[(size_t)(63 + 2 * i) * BATCH + b];
        float g6b = g_gates[(size_t)(63 + 2 * i + 1) * BATCH + b];
        float c0 = a0 * g6a, c1 = a0 - c0;
        float c2 = a1 * g6b, c3 = a1 - c2;
        float q[4] = {c0, c1, c2, c3};
#pragma unroll
        for (int j = 0; j < 4; ++j) {
            float g7 = g_gates[(size_t)(127 + 4 * i + j) * BATCH + b];
            float e0 = q[j] * g7;
            float e1 = q[j] - e0;
            int leaf = 8 * i + 2 * j;
            lp[(size_t)leaf * BATCH + b]       = e0;
            lp[(size_t)(leaf + 1) * BATCH + b] = e1;
        }
    }
}

// ---------------------------------------------------------------------------
// Kernel 3: main GEMM  out[l][b][o] = act(X @ PW_l + pb_l)
// tf32 mma.sync.m16n8k8, fp32 accumulate.
// CTA: 256 threads (8 warps). Tile M=128, N=128 (= 2 leaves x 64), BK=32.
// Warp tile 32(M) x 64(N): warp grid 4(M) x 2(N).
// Smem: Xs[m][k] stride 36 (conflict-free A-frag loads: bank = 4g+t, distinct),
//       Ws[k][n] stride 132 (conflict-free stores, ~2-way frag loads).
// grid (128 m-tiles, 128 leaf-pairs)
// ---------------------------------------------------------------------------
__global__ __launch_bounds__(256, 2) void moe_gemm_kernel(
    const float* __restrict__ x, const float* __restrict__ pw,
    const float* __restrict__ pb, float* __restrict__ out)
{
    __shared__ __align__(16) float Xs[128][36];
    __shared__ __align__(16) float Ws[32][132];

    const int tid  = threadIdx.x;
    const int bm   = blockIdx.x;    // 0..127
    const int pair = blockIdx.y;    // 0..127
    const int warp = tid >> 5, lane = tid & 31;
    const int wm = warp & 3, wn = warp >> 2;
    const int g = lane >> 2, t = lane & 3;

    float acc[2][8][4];
#pragma unroll
    for (int mi = 0; mi < 2; ++mi)
#pragma unroll
        for (int ni = 0; ni < 8; ++ni)
#pragma unroll
            for (int r = 0; r < 4; ++r) acc[mi][ni][r] = 0.0f;

    const int xr  = tid >> 3;         // 0..31
    const int xc  = (tid & 7) * 4;    // 0..28
    const int wn4 = (tid & 15) * 4;   // 0..60
    const int wkk = tid >> 4;         // 0..15

    const float* xblk = x + (size_t)bm * 128 * IN_F;
    const float* wblk = pw + (size_t)pair * 2 * IN_F * OUT_F;

    for (int kt = 0; kt < IN_F; kt += 32) {
        __syncthreads();
        // X tile 128 x 32 (cvt.rna -> tf32 at stage time)
#pragma unroll
        for (int i = 0; i < 4; ++i) {
            float4 v = *reinterpret_cast<const float4*>(
                &xblk[(size_t)(xr + 32 * i) * IN_F + kt + xc]);
            v.x = to_tf32(v.x); v.y = to_tf32(v.y);
            v.z = to_tf32(v.z); v.w = to_tf32(v.w);
            *reinterpret_cast<float4*>(&Xs[xr + 32 * i][xc]) = v;
        }
        // W tile: 2 leaves x [32 k x 64 n]
#pragma unroll
        for (int ls = 0; ls < 2; ++ls)
#pragma unroll
            for (int ss = 0; ss < 2; ++ss) {
                int k = kt + wkk + 16 * ss;
                float4 v = *reinterpret_cast<const float4*>(
                    &wblk[((size_t)ls * IN_F + k) * OUT_F + wn4]);
                v.x = to_tf32(v.x); v.y = to_tf32(v.y);
                v.z = to_tf32(v.z); v.w = to_tf32(v.w);
                *reinterpret_cast<float4*>(&Ws[wkk + 16 * ss][ls * 64 + wn4]) = v;
            }
        __syncthreads();

#pragma unroll
        for (int s = 0; s < 4; ++s) {
            uint32_t af[2][4];
            const int kc = s * 8 + t;
#pragma unroll
            for (int mi = 0; mi < 2; ++mi) {
                int rm = wm * 32 + mi * 16;
                af[mi][0] = __float_as_uint(Xs[rm + g][kc]);
                af[mi][1] = __float_as_uint(Xs[rm + g + 8][kc]);
                af[mi][2] = __float_as_uint(Xs[rm + g][kc + 4]);
                af[mi][3] = __float_as_uint(Xs[rm + g + 8][kc + 4]);
            }
#pragma unroll
            for (int ni = 0; ni < 8; ++ni) {
                int cn = wn * 64 + ni * 8 + g;
                uint32_t b0 = __float_as_uint(Ws[s * 8 + t][cn]);
                uint32_t b1 = __float_as_uint(Ws[s * 8 + t + 4][cn]);
                mma_tf32(acc[0][ni], af[0], b0, b1);
                mma_tf32(acc[1][ni], af[1], b0, b1);
            }
        }
    }

    // Epilogue: +pb, activation, store
    const int leaf = pair * 2 + wn;
#pragma unroll
    for (int mi = 0; mi < 2; ++mi) {
        int row0 = bm * 128 + wm * 32 + mi * 16 + g;
#pragma unroll
        for (int ni = 0; ni < 8; ++ni) {
            int o = ni * 8 + 2 * t;
            float pb0 = pb[leaf * 64 + o];
            float pb1 = pb[leaf * 64 + o + 1];
            size_t base  = ((size_t)leaf * BATCH + row0) * OUT_F + o;
            size_t base2 = base + (size_t)8 * OUT_F;   // row0 + 8
            out[base]      = activate(acc[mi][ni][0] + pb0, o);
            out[base + 1]  = activate(acc[mi][ni][1] + pb1, o + 1);
            out[base2]     = activate(acc[mi][ni][2] + pb0, o);
            out[base2 + 1] = activate(acc[mi][ni][3] + pb1, o + 1);
        }
    }
}

// ---------------------------------------------------------------------------
extern "C" void kernel_launch(void* const* d_in, const int* in_sizes, int n_in,
                              void* d_out, int out_size)
{
    const float* x  = (const float*)d_in[0];
    const float* gw = (const float*)d_in[1];
    const float* gb = (const float*)d_in[2];
    const float* pw = (const float*)d_in[3];
    const float* pb = (const float*)d_in[4];

    float* out = (float*)d_out;
    float* lp  = out + (size_t)LEAVES * BATCH * OUT_F;   // leaf_probs region

    gates_kernel<<<dim3(4, 256), 256>>>(x, gw, gb);
    leaf_kernel<<<64, 256>>>(lp);
    moe_gemm_kernel<<<dim3(128, 128), 256>>>(x, pw, pb, out);
}

// round 3
// speedup vs baseline: 1.6261x; 1.6261x over previous
#include <cuda_runtime.h>
#include <cstdint>

#define BATCH   16384
#define IN_F    512
#define OUT_F   64
#define LEAVES  256
#define GATES   255
#define PI_F    3.14159265358979323846f

// Scratch (device globals; no allocation allowed)
__device__ float g_gates[GATES * BATCH];                 // sigmoid gates [gate][batch]
__device__ float g_xR[BATCH * IN_F];                     // tf32-rounded X
__device__ float g_wR[LEAVES * IN_F * OUT_F];            // tf32-rounded W [leaf][k][o]

// ---------------------------------------------------------------------------
// helpers
// ---------------------------------------------------------------------------
__device__ __forceinline__ float to_tf32(float x) {
    uint32_t u;
    asm("cvt.rna.tf32.f32 %0, %1;" : "=r"(u) : "f"(x));
    return __uint_as_float(u);
}
__device__ __forceinline__ float sigmoid_f(float z) {
    return __fdividef(1.0f, 1.0f + __expf(-z));
}
__device__ __forceinline__ float tanhpi_f(float z) {
    float e = __expf(2.0f * z);
    return (1.0f - __fdividef(2.0f, e + 1.0f)) * PI_F;
}
__device__ __forceinline__ uint32_t smem_u32(const void* p) {
    uint32_t a;
    asm("{ .reg .u64 t; cvta.to.shared.u64 t, %1; cvt.u32.u64 %0, t; }"
        : "=r"(a) : "l"(p));
    return a;
}
__device__ __forceinline__ void cp16(uint32_t dst, const float* src) {
    asm volatile("cp.async.cg.shared.global [%0], [%1], 16;"
                 :: "r"(dst), "l"(__cvta_generic_to_global(src)));
}
__device__ __forceinline__ void mma_tf32(float c[4], const uint32_t a[4],
                                         uint32_t b0, uint32_t b1) {
    asm volatile(
        "mma.sync.aligned.m16n8k8.row.col.f32.tf32.tf32.f32 "
        "{%0,%1,%2,%3}, {%4,%5,%6,%7}, {%8,%9}, {%0,%1,%2,%3};\n"
        : "+f"(c[0]), "+f"(c[1]), "+f"(c[2]), "+f"(c[3])
        : "r"(a[0]), "r"(a[1]), "r"(a[2]), "r"(a[3]), "r"(b0), "r"(b1));
}

// ---------------------------------------------------------------------------
// Pre-pass: tf32 (rna) rounding of X and W
// ---------------------------------------------------------------------------
__global__ __launch_bounds__(256) void xround_kernel(const float* __restrict__ x) {
    int i = blockIdx.x * 256 + threadIdx.x;
    float4 v = reinterpret_cast<const float4*>(x)[i];
    v.x = to_tf32(v.x); v.y = to_tf32(v.y);
    v.z = to_tf32(v.z); v.w = to_tf32(v.w);
    reinterpret_cast<float4*>(g_xR)[i] = v;
}
__global__ __launch_bounds__(256) void wround_kernel(const float* __restrict__ pw) {
    int i = blockIdx.x * 256 + threadIdx.x;
    float4 v = reinterpret_cast<const float4*>(pw)[i];
    v.x = to_tf32(v.x); v.y = to_tf32(v.y);
    v.z = to_tf32(v.z); v.w = to_tf32(v.w);
    reinterpret_cast<float4*>(g_wR)[i] = v;
}

// ---------------------------------------------------------------------------
// Gate GEMM (fp32 exact) -> sigmoid -> g_gates[gate][batch]
// 64x64 tile, BK=16, register double-buffer + smem ping-pong.
// ---------------------------------------------------------------------------
__global__ __launch_bounds__(256) void gates_kernel(
    const float* __restrict__ x, const float* __restrict__ gw,
    const float* __restrict__ gb)
{
    __shared__ __align__(16) float As[2][16][68];   // [k][m]
    __shared__ __align__(16) float Bs[2][16][68];   // [k][n]

    const int tid = threadIdx.x;
    const int nb = blockIdx.x;
    const int mb = blockIdx.y;
    const int tx = tid & 15, ty = tid >> 4;

    float acc[4][4];
#pragma unroll
    for (int i = 0; i < 4; ++i)
#pragma unroll
        for (int j = 0; j < 4; ++j) acc[i][j] = 0.0f;

    const int xr = tid >> 2;          // 0..63
    const int xc = (tid & 3) * 4;     // 0,4,8,12
    const int wr = tid >> 4;          // 0..15
    const int wc = (tid & 15) * 4;    // 0..60

    // prologue: tile 0
    float4 xa = *reinterpret_cast<const float4*>(&x[(size_t)(mb * 64 + xr) * IN_F + xc]);
    float wv[4];
#pragma unroll
    for (int j = 0; j < 4; ++j) {
        int n = nb * 64 + wc + j;
        wv[j] = (n < GATES) ? gw[(size_t)wr * GATES + n] : 0.0f;
    }
    As[0][xc + 0][xr] = xa.x; As[0][xc + 1][xr] = xa.y;
    As[0][xc + 2][xr] = xa.z; As[0][xc + 3][xr] = xa.w;
#pragma unroll
    for (int j = 0; j < 4; ++j) Bs[0][wr][wc + j] = wv[j];
    __syncthreads();

    int buf = 0;
    for (int it = 0; it < 32; ++it) {
        const int kt = (it + 1) * 16;
        if (it < 31) {
            xa = *reinterpret_cast<const float4*>(
                &x[(size_t)(mb * 64 + xr) * IN_F + kt + xc]);
#pragma unroll
            for (int j = 0; j < 4; ++j) {
                int n = nb * 64 + wc + j;
                wv[j] = (n < GATES) ? gw[(size_t)(kt + wr) * GATES + n] : 0.0f;
            }
        }
#pragma unroll
        for (int k = 0; k < 16; ++k) {
            float a[4], b[4];
            *reinterpret_cast<float4*>(a) = *reinterpret_cast<float4*>(&As[buf][k][ty * 4]);
            *reinterpret_cast<float4*>(b) = *reinterpret_cast<float4*>(&Bs[buf][k][tx * 4]);
#pragma unroll
            for (int i = 0; i < 4; ++i)
#pragma unroll
                for (int j = 0; j < 4; ++j) acc[i][j] += a[i] * b[j];
        }
        if (it < 31) {
            int nb2 = buf ^ 1;
            As[nb2][xc + 0][xr] = xa.x; As[nb2][xc + 1][xr] = xa.y;
            As[nb2][xc + 2][xr] = xa.z; As[nb2][xc + 3][xr] = xa.w;
#pragma unroll
            for (int j = 0; j < 4; ++j) Bs[nb2][wr][wc + j] = wv[j];
            __syncthreads();
            buf = nb2;
        }
    }

#pragma unroll
    for (int j = 0; j < 4; ++j) {
        int n = nb * 64 + tx * 4 + j;
        if (n >= GATES) continue;
        float gbv = gb[n];
#pragma unroll
        for (int i = 0; i < 4; ++i) {
            int b = mb * 64 + ty * 4 + i;
            g_gates[(size_t)n * BATCH + b] = sigmoid_f(acc[i][j] + gbv);
        }
    }
}

// ---------------------------------------------------------------------------
// Leaf probabilities
// ---------------------------------------------------------------------------
__global__ __launch_bounds__(256) void leaf_kernel(float* __restrict__ lp)
{
    const int b = blockIdx.x * 256 + threadIdx.x;

    float dens[32];
    dens[0] = 1.0f;
#pragma unroll
    for (int d = 0; d < 5; ++d) {
        const int width = 1 << d;
        const int base = width - 1;
#pragma unroll
        for (int i = width - 1; i >= 0; --i) {
            float g = g_gates[(size_t)(base + i) * BATCH + b];
            float v = dens[i];
            float vg = v * g;
            dens[2 * i]     = vg;
            dens[2 * i + 1] = v - vg;
        }
    }
#pragma unroll
    for (int i = 0; i < 32; ++i) {
        float p  = dens[i];
        float g5 = g_gates[(size_t)(31 + i) * BATCH + b];
        float a0 = p * g5, a1 = p - a0;
        float g6a = g_gates[(size_t)(63 + 2 * i) * BATCH + b];
        float g6b = g_gates[(size_t)(63 + 2 * i + 1) * BATCH + b];
        float c0 = a0 * g6a, c1 = a0 - c0;
        float c2 = a1 * g6b, c3 = a1 - c2;
        float q[4] = {c0, c1, c2, c3};
#pragma unroll
        for (int j = 0; j < 4; ++j) {
            float g7 = g_gates[(size_t)(127 + 4 * i + j) * BATCH + b];
            float e0 = q[j] * g7;
            float e1 = q[j] - e0;
            int leaf = 8 * i + 2 * j;
            lp[(size_t)leaf * BATCH + b]       = e0;
            lp[(size_t)(leaf + 1) * BATCH + b] = e1;
        }
    }
}

// ---------------------------------------------------------------------------
// Main GEMM: tf32 mma.sync m16n8k8, cp.async 4-stage pipeline.
// CTA: 512 threads (16 warps). Tile M=256 (batch) x N=128 (2 leaves), BK=16.
// Warp grid 4(M) x 4(N), warp tile 64x32.
// Smem: Xs[m][k] stride 20 words (conflict-free A frags),
//       Ws[k][n] stride 136 words (conflict-free B frags).
// ---------------------------------------------------------------------------
#define STAGES      4
#define STAGE_WORDS 7296            // 256*20 + 16*136
#define WOFF_WORDS  5120            // 256*20
#define STAGE_BYTES (STAGE_WORDS * 4)
#define DYN_SMEM    (STAGES * STAGE_BYTES)

__device__ __forceinline__ void moe_load_stage(float* sm, uint32_t sm_b, int slot,
                                               int kt, int bm, int pair, int tid) {
    const uint32_t sb = sm_b + slot * STAGE_BYTES;
    // X: 256 rows x 16 k -> 1024 16B chunks
#pragma unroll
    for (int i = 0; i < 2; ++i) {
        int c = tid + i * 512;
        int m = c >> 2, q = c & 3;
        cp16(sb + (m * 20 + q * 4) * 4,
             g_xR + (size_t)(bm * 256 + m) * IN_F + kt + q * 4);
    }
    // W: 16 k x 128 n -> 512 chunks
    {
        int k = tid >> 5, q = tid & 31;
        int leaf = pair * 2 + (q >> 4);
        int o = (q & 15) * 4;
        cp16(sb + (WOFF_WORDS + k * 136 + q * 4) * 4,
             g_wR + ((size_t)leaf * IN_F + kt + k) * OUT_F + o);
    }
    asm volatile("cp.async.commit_group;" ::: "memory");
}

__global__ __launch_bounds__(512, 1) void moe_gemm_kernel(
    const float* __restrict__ pb, float* __restrict__ out)
{
    extern __shared__ float sm[];
    const uint32_t sm_b = smem_u32(sm);

    const int tid  = threadIdx.x;
    const int bm   = blockIdx.x;    // 0..63
    const int pair = blockIdx.y;    // 0..127
    const int warp = tid >> 5, lane = tid & 31;
    const int wm = warp & 3, wn = warp >> 2;
    const int g = lane >> 2, t = lane & 3;

    float acc[4][4][4];
#pragma unroll
    for (int mi = 0; mi < 4; ++mi)
#pragma unroll
        for (int ni = 0; ni < 4; ++ni)
#pragma unroll
            for (int r = 0; r < 4; ++r) acc[mi][ni][r] = 0.0f;

    // prologue: stages 0..2
    moe_load_stage(sm, sm_b, 0, 0, bm, pair, tid);
    moe_load_stage(sm, sm_b, 1, 16, bm, pair, tid);
    moe_load_stage(sm, sm_b, 2, 32, bm, pair, tid);

    for (int it = 0; it < 32; ++it) {
        const int slot = it & 3;
        asm volatile("cp.async.wait_group %0;" :: "n"(STAGES - 2) : "memory");
        __syncthreads();
        if (it + 3 < 32)
            moe_load_stage(sm, sm_b, (it + 3) & 3, (it + 3) * 16, bm, pair, tid);
        else
            asm volatile("cp.async.commit_group;" ::: "memory");

        const float* Xs = sm + slot * STAGE_WORDS;
        const float* Ws = sm + slot * STAGE_WORDS + WOFF_WORDS;
#pragma unroll
        for (int s = 0; s < 2; ++s) {
            const int k8 = s * 8;
            uint32_t af[4][4];
#pragma unroll
            for (int mi = 0; mi < 4; ++mi) {
                const int rm = wm * 64 + mi * 16 + g;
                af[mi][0] = __float_as_uint(Xs[rm * 20 + k8 + t]);
                af[mi][1] = __float_as_uint(Xs[(rm + 8) * 20 + k8 + t]);
                af[mi][2] = __float_as_uint(Xs[rm * 20 + k8 + t + 4]);
                af[mi][3] = __float_as_uint(Xs[(rm + 8) * 20 + k8 + t + 4]);
            }
#pragma unroll
            for (int ni = 0; ni < 4; ++ni) {
                const int cn = wn * 32 + ni * 8 + g;
                uint32_t b0 = __float_as_uint(Ws[(k8 + t) * 136 + cn]);
                uint32_t b1 = __float_as_uint(Ws[(k8 + t + 4) * 136 + cn]);
#pragma unroll
                for (int mi = 0; mi < 4; ++mi)
                    mma_tf32(acc[mi][ni], af[mi], b0, b1);
            }
        }
    }

    // Epilogue: +pb, activation, store. o block constant per warp (wn&1).
    const int leaf = pair * 2 + (wn >> 1);
    const bool is_tanh = !(wn & 1);
    float pb0[4], pb1[4];
#pragma unroll
    for (int ni = 0; ni < 4; ++ni) {
        int o = (wn & 1) * 32 + ni * 8 + 2 * t;
        pb0[ni] = pb[leaf * 64 + o];
        pb1[ni] = pb[leaf * 64 + o + 1];
    }

#pragma unroll
    for (int mi = 0; mi < 4; ++mi) {
        const int row0 = bm * 256 + wm * 64 + mi * 16 + g;
#pragma unroll
        for (int ni = 0; ni < 4; ++ni) {
            const int o = (wn & 1) * 32 + ni * 8 + 2 * t;
            float v0 = acc[mi][ni][0] + pb0[ni];
            float v1 = acc[mi][ni][1] + pb1[ni];
            float v2 = acc[mi][ni][2] + pb0[ni];
            float v3 = acc[mi][ni][3] + pb1[ni];
            if (is_tanh) {
                v0 = tanhpi_f(v0); v1 = tanhpi_f(v1);
                v2 = tanhpi_f(v2); v3 = tanhpi_f(v3);
            } else {
                v0 = sigmoid_f(v0); v1 = sigmoid_f(v1);
                v2 = sigmoid_f(v2); v3 = sigmoid_f(v3);
            }
            float2* p0 = reinterpret_cast<float2*>(
                out + ((size_t)leaf * BATCH + row0) * OUT_F + o);
            float2* p1 = reinterpret_cast<float2*>(
                out + ((size_t)leaf * BATCH + row0 + 8) * OUT_F + o);
            *p0 = make_float2(v0, v1);
            *p1 = make_float2(v2, v3);
        }
    }
}

// ---------------------------------------------------------------------------
extern "C" void kernel_launch(void* const* d_in, const int* in_sizes, int n_in,
                              void* d_out, int out_size)
{
    const float* x  = (const float*)d_in[0];
    const float* gw = (const float*)d_in[1];
    const float* gb = (const float*)d_in[2];
    const float* pw = (const float*)d_in[3];
    const float* pb = (const float*)d_in[4];

    float* out = (float*)d_out;
    float* lp  = out + (size_t)LEAVES * BATCH * OUT_F;

    cudaFuncSetAttribute(moe_gemm_kernel,
                         cudaFuncAttributeMaxDynamicSharedMemorySize, DYN_SMEM);

    xround_kernel<<<BATCH * IN_F / 4 / 256, 256>>>(x);
    wround_kernel<<<LEAVES * IN_F * OUT_F / 4 / 256, 256>>>(pw);
    gates_kernel<<<dim3(4, 256), 256>>>(x, gw, gb);
    leaf_kernel<<<64, 256>>>(lp);
    moe_gemm_kernel<<<dim3(64, 128), 512, DYN_SMEM>>>(pb, out);
}

// round 6
// speedup vs baseline: 2.1122x; 1.2990x over previous
#include <cuda_runtime.h>
#include <cstdint>

#define BATCH   16384
#define IN_F    512
#define OUT_F   64
#define LEAVES  256
#define GATES   255
#define PI_F    3.14159265358979323846f

// Scratch (device globals; no allocation allowed)
__device__ float g_gates[GATES * BATCH];              // sigmoid gates [gate][batch]
__device__ float g_xF[BATCH * IN_F];                  // fragment-ordered tf32 X
__device__ float g_wF[LEAVES * IN_F * OUT_F];         // fragment-ordered tf32 W

// ---------------------------------------------------------------------------
// helpers
// ---------------------------------------------------------------------------
__device__ __forceinline__ float to_tf32(float x) {
    uint32_t u;
    asm("cvt.rna.tf32.f32 %0, %1;" : "=r"(u) : "f"(x));
    return __uint_as_float(u);
}
__device__ __forceinline__ float sigmoid_f(float z) {
    return __fdividef(1.0f, 1.0f + __expf(-z));
}
__device__ __forceinline__ float tanhpi_f(float z) {
    float e = __expf(2.0f * z);
    return (1.0f - __fdividef(2.0f, e + 1.0f)) * PI_F;
}
__device__ __forceinline__ uint32_t smem_u32(const void* p) {
    uint32_t a;
    asm("{ .reg .u64 t; cvta.to.shared.u64 t, %1; cvt.u32.u64 %0, t; }"
        : "=r"(a) : "l"(p));
    return a;
}
__device__ __forceinline__ void cp16(uint32_t dst, const float* src) {
    asm volatile("cp.async.cg.shared.global [%0], [%1], 16;"
                 :: "r"(dst), "l"(__cvta_generic_to_global(src)));
}
__device__ __forceinline__ void mma_tf32(float c[4], const float4 a, float b0, float b1) {
    asm volatile(
        "mma.sync.aligned.m16n8k8.row.col.f32.tf32.tf32.f32 "
        "{%0,%1,%2,%3}, {%4,%5,%6,%7}, {%8,%9}, {%0,%1,%2,%3};\n"
        : "+f"(c[0]), "+f"(c[1]), "+f"(c[2]), "+f"(c[3])
        : "r"(__float_as_uint(a.x)), "r"(__float_as_uint(a.y)),
          "r"(__float_as_uint(a.z)), "r"(__float_as_uint(a.w)),
          "r"(__float_as_uint(b0)), "r"(__float_as_uint(b1)));
}

// ---------------------------------------------------------------------------
// Pre-pass: X -> fragment order (tf32 rna)
// g_xF[((mb16*64 + kb8)*32 + lane)*4 + r]
// lane = 4g+t; frag = {X[R+g][K+t], X[R+g+8][K+t], X[R+g][K+t+4], X[R+g+8][K+t+4]}
// ---------------------------------------------------------------------------
__global__ __launch_bounds__(256) void xfrag_kernel(const float* __restrict__ x) {
    const int tg = blockIdx.x * 256 + threadIdx.x;   // float4 index, 0..2M-1
    const int lane = tg & 31;
    const int kb8  = (tg >> 5) & 63;
    const int mb16 = tg >> 11;
    const int g = lane >> 2, t = lane & 3;
    const int R = mb16 * 16, K = kb8 * 8;
    float4 v;
    v.x = to_tf32(x[(size_t)(R + g)     * IN_F + K + t]);
    v.y = to_tf32(x[(size_t)(R + g + 8) * IN_F + K + t]);
    v.z = to_tf32(x[(size_t)(R + g)     * IN_F + K + t + 4]);
    v.w = to_tf32(x[(size_t)(R + g + 8) * IN_F + K + t + 4]);
    reinterpret_cast<float4*>(g_xF)[tg] = v;
}

// ---------------------------------------------------------------------------
// Pre-pass: W -> fragment order (tf32 rna)
// g_wF[(((leaf*8 + n8)*64 + kb8)*32 + lane)*2 + r]
// frag = {W[l][K+t][N8+g], W[l][K+t+4][N8+g]}
// NOTE: one float2 per thread -> grid must cover LEAVES*IN_F*OUT_F/2 threads.
// ---------------------------------------------------------------------------
__global__ __launch_bounds__(256) void wfrag_kernel(const float* __restrict__ pw) {
    const int tg = blockIdx.x * 256 + threadIdx.x;   // float2 index, 0..4.19M-1
    const int lane = tg & 31;
    const int kb8  = (tg >> 5) & 63;
    const int n8   = (tg >> 11) & 7;
    const int leaf = tg >> 14;
    const int g = lane >> 2, t = lane & 3;
    const int K = kb8 * 8, N8 = n8 * 8;
    float2 v;
    v.x = to_tf32(pw[((size_t)leaf * IN_F + K + t)     * OUT_F + N8 + g]);
    v.y = to_tf32(pw[((size_t)leaf * IN_F + K + t + 4) * OUT_F + N8 + g]);
    reinterpret_cast<float2*>(g_wF)[tg] = v;
}

// ---------------------------------------------------------------------------
// Gate GEMM (fp32 exact) -> sigmoid -> g_gates[gate][batch]
// ---------------------------------------------------------------------------
__global__ __launch_bounds__(256) void gates_kernel(
    const float* __restrict__ x, const float* __restrict__ gw,
    const float* __restrict__ gb)
{
    __shared__ __align__(16) float As[2][16][68];
    __shared__ __align__(16) float Bs[2][16][68];

    const int tid = threadIdx.x;
    const int nb = blockIdx.x;
    const int mb = blockIdx.y;
    const int tx = tid & 15, ty = tid >> 4;

    float acc[4][4];
#pragma unroll
    for (int i = 0; i < 4; ++i)
#pragma unroll
        for (int j = 0; j < 4; ++j) acc[i][j] = 0.0f;

    const int xr = tid >> 2;
    const int xc = (tid & 3) * 4;
    const int wr = tid >> 4;
    const int wc = (tid & 15) * 4;

    float4 xa = *reinterpret_cast<const float4*>(&x[(size_t)(mb * 64 + xr) * IN_F + xc]);
    float wv[4];
#pragma unroll
    for (int j = 0; j < 4; ++j) {
        int n = nb * 64 + wc + j;
        wv[j] = (n < GATES) ? gw[(size_t)wr * GATES + n] : 0.0f;
    }
    As[0][xc + 0][xr] = xa.x; As[0][xc + 1][xr] = xa.y;
    As[0][xc + 2][xr] = xa.z; As[0][xc + 3][xr] = xa.w;
#pragma unroll
    for (int j = 0; j < 4; ++j) Bs[0][wr][wc + j] = wv[j];
    __syncthreads();

    int buf = 0;
    for (int it = 0; it < 32; ++it) {
        const int kt = (it + 1) * 16;
        if (it < 31) {
            xa = *reinterpret_cast<const float4*>(
                &x[(size_t)(mb * 64 + xr) * IN_F + kt + xc]);
#pragma unroll
            for (int j = 0; j < 4; ++j) {
                int n = nb * 64 + wc + j;
                wv[j] = (n < GATES) ? gw[(size_t)(kt + wr) * GATES + n] : 0.0f;
            }
        }
#pragma unroll
        for (int k = 0; k < 16; ++k) {
            float a[4], b[4];
            *reinterpret_cast<float4*>(a) = *reinterpret_cast<float4*>(&As[buf][k][ty * 4]);
            *reinterpret_cast<float4*>(b) = *reinterpret_cast<float4*>(&Bs[buf][k][tx * 4]);
#pragma unroll
            for (int i = 0; i < 4; ++i)
#pragma unroll
                for (int j = 0; j < 4; ++j) acc[i][j] += a[i] * b[j];
        }
        if (it < 31) {
            int nb2 = buf ^ 1;
            As[nb2][xc + 0][xr] = xa.x; As[nb2][xc + 1][xr] = xa.y;
            As[nb2][xc + 2][xr] = xa.z; As[nb2][xc + 3][xr] = xa.w;
#pragma unroll
            for (int j = 0; j < 4; ++j) Bs[nb2][wr][wc + j] = wv[j];
            __syncthreads();
            buf = nb2;
        }
    }

#pragma unroll
    for (int j = 0; j < 4; ++j) {
        int n = nb * 64 + tx * 4 + j;
        if (n >= GATES) continue;
        float gbv = gb[n];
#pragma unroll
        for (int i = 0; i < 4; ++i) {
            int b = mb * 64 + ty * 4 + i;
            g_gates[(size_t)n * BATCH + b] = sigmoid_f(acc[i][j] + gbv);
        }
    }
}

// ---------------------------------------------------------------------------
// Leaf probabilities
// ---------------------------------------------------------------------------
__global__ __launch_bounds__(256) void leaf_kernel(float* __restrict__ lp)
{
    const int b = blockIdx.x * 256 + threadIdx.x;

    float dens[32];
    dens[0] = 1.0f;
#pragma unroll
    for (int d = 0; d < 5; ++d) {
        const int width = 1 << d;
        const int base = width - 1;
#pragma unroll
        for (int i = width - 1; i >= 0; --i) {
            float g = g_gates[(size_t)(base + i) * BATCH + b];
            float v = dens[i];
            float vg = v * g;
            dens[2 * i]     = vg;
            dens[2 * i + 1] = v - vg;
        }
    }
#pragma unroll
    for (int i = 0; i < 32; ++i) {
        float p  = dens[i];
        float g5 = g_gates[(size_t)(31 + i) * BATCH + b];
        float a0 = p * g5, a1 = p - a0;
        float g6a = g_gates[(size_t)(63 + 2 * i) * BATCH + b];
        float g6b = g_gates[(size_t)(63 + 2 * i + 1) * BATCH + b];
        float c0 = a0 * g6a, c1 = a0 - c0;
        float c2 = a1 * g6b, c3 = a1 - c2;
        float q[4] = {c0, c1, c2, c3};
#pragma unroll
        for (int j = 0; j < 4; ++j) {
            float g7 = g_gates[(size_t)(127 + 4 * i + j) * BATCH + b];
            float e0 = q[j] * g7;
            float e1 = q[j] - e0;
            int leaf = 8 * i + 2 * j;
            lp[(size_t)leaf * BATCH + b]       = e0;
            lp[(size_t)(leaf + 1) * BATCH + b] = e1;
        }
    }
}

// ---------------------------------------------------------------------------
// Main GEMM: tf32 mma.sync m16n8k8, fragment-order smem, 4-stage cp.async.
// CTA: 256 threads (8 warps). Tile M=128 x N=256 (4 leaves), BK=16/stage.
// Warp grid 2(M) x 4(N); warp tile 64x64 (mi=4 m16-blocks, ni=8 n8-blocks).
// Stage smem: X 8KB + W 16KB = 24KB; 4 stages = 96KB.
// ---------------------------------------------------------------------------
#define STAGE_BYTES 24576
#define STAGE_WORDS 6144
#define XW_WORDS    2048              // X words per stage
#define DYN_SMEM    (4 * STAGE_BYTES)

__device__ __forceinline__ void moe_load_stage(uint32_t sm_b, int slot, int kt16,
                                               int bm, int lg, int tid) {
    const uint32_t sb = sm_b + slot * STAGE_BYTES;
    // X: 512 x 16B chunks; chunk c = (mb16l*2 + kb8l)*32 + lane
#pragma unroll
    for (int i = 0; i < 2; ++i) {
        const int c = tid + i * 256;
        const int mb16l = c >> 6, rem = c & 63;      // rem = kb8l*32 + lane
        cp16(sb + c * 16,
             g_xF + ((((size_t)(bm * 8 + mb16l) * 64) + kt16 * 2) * 32 + rem) * 4);
    }
    // W: 1024 x 16B chunks (2 lanes each); c = ((leafl*8+n8)*2 + kb8l)*16 + p
#pragma unroll
    for (int i = 0; i < 4; ++i) {
        const int c = tid + i * 256;
        const int leafl = c >> 8;
        const int n8    = (c >> 5) & 7;
        const int rem   = c & 31;                    // kb8l*16 + p
        cp16(sb + 8192 + c * 16,
             g_wF + ((((size_t)(lg * 4 + leafl) * 8 + n8) * 64 + kt16 * 2) * 32
                     + rem * 2) * 2);
    }
    asm volatile("cp.async.commit_group;" ::: "memory");
}

__global__ __launch_bounds__(256, 1) void moe_gemm_kernel(
    const float* __restrict__ pb, float* __restrict__ out)
{
    extern __shared__ float sm[];
    const uint32_t sm_b = smem_u32(sm);

    const int tid  = threadIdx.x;
    const int bm   = blockIdx.x;    // 0..127 (M tiles of 128)
    const int lg   = blockIdx.y;    // 0..63  (leaf groups of 4)
    const int warp = tid >> 5, lane = tid & 31;
    const int wm = warp & 1, wn = warp >> 1;
    const int g = lane >> 2, t = lane & 3;

    float acc[4][8][4];
#pragma unroll
    for (int mi = 0; mi < 4; ++mi)
#pragma unroll
        for (int ni = 0; ni < 8; ++ni)
#pragma unroll
            for (int r = 0; r < 4; ++r) acc[mi][ni][r] = 0.0f;

    moe_load_stage(sm_b, 0, 0, bm, lg, tid);
    moe_load_stage(sm_b, 1, 1, bm, lg, tid);
    moe_load_stage(sm_b, 2, 2, bm, lg, tid);

#pragma unroll 4
    for (int it = 0; it < 32; ++it) {
        const int slot = it & 3;
        asm volatile("cp.async.wait_group 2;" ::: "memory");
        __syncthreads();
        if (it + 3 < 32)
            moe_load_stage(sm_b, (it + 3) & 3, it + 3, bm, lg, tid);
        else
            asm volatile("cp.async.commit_group;" ::: "memory");

        const float* Xs = sm + slot * STAGE_WORDS;
        const float* Ws = Xs + XW_WORDS;

#pragma unroll
        for (int s = 0; s < 2; ++s) {
            float4 a[4];
#pragma unroll
            for (int mi = 0; mi < 4; ++mi)
                a[mi] = *reinterpret_cast<const float4*>(
                    Xs + (((wm * 4 + mi) * 2 + s) * 32 + lane) * 4);
#pragma unroll
            for (int ni = 0; ni < 8; ++ni) {
                float2 b = *reinterpret_cast<const float2*>(
                    Ws + (((wn * 8 + ni) * 2 + s) * 32 + lane) * 2);
#pragma unroll
                for (int mi = 0; mi < 4; ++mi)
                    mma_tf32(acc[mi][ni], a[mi], b.x, b.y);
            }
        }
    }

    // Epilogue: +pb, activation, store (leaf = lg*4 + wn; warp owns full leaf)
    const int leaf = lg * 4 + wn;
    float pb0[8], pb1[8];
#pragma unroll
    for (int ni = 0; ni < 8; ++ni) {
        const int o = ni * 8 + 2 * t;
        pb0[ni] = pb[leaf * 64 + o];
        pb1[ni] = pb[leaf * 64 + o + 1];
    }

#pragma unroll
    for (int mi = 0; mi < 4; ++mi) {
        const int row0 = bm * 128 + wm * 64 + mi * 16 + g;
#pragma unroll
        for (int ni = 0; ni < 8; ++ni) {
            const int o = ni * 8 + 2 * t;
            const bool is_tanh = (ni < 4);
            float v0 = acc[mi][ni][0] + pb0[ni];
            float v1 = acc[mi][ni][1] + pb1[ni];
            float v2 = acc[mi][ni][2] + pb0[ni];
            float v3 = acc[mi][ni][3] + pb1[ni];
            if (is_tanh) {
                v0 = tanhpi_f(v0); v1 = tanhpi_f(v1);
                v2 = tanhpi_f(v2); v3 = tanhpi_f(v3);
            } else {
                v0 = sigmoid_f(v0); v1 = sigmoid_f(v1);
                v2 = sigmoid_f(v2); v3 = sigmoid_f(v3);
            }
            *reinterpret_cast<float2*>(
                out + ((size_t)leaf * BATCH + row0) * OUT_F + o) = make_float2(v0, v1);
            *reinterpret_cast<float2*>(
                out + ((size_t)leaf * BATCH + row0 + 8) * OUT_F + o) = make_float2(v2, v3);
        }
    }
}

// ---------------------------------------------------------------------------
extern "C" void kernel_launch(void* const* d_in, const int* in_sizes, int n_in,
                              void* d_out, int out_size)
{
    const float* x  = (const float*)d_in[0];
    const float* gw = (const float*)d_in[1];
    const float* gb = (const float*)d_in[2];
    const float* pw = (const float*)d_in[3];
    const float* pb = (const float*)d_in[4];

    float* out = (float*)d_out;
    float* lp  = out + (size_t)LEAVES * BATCH * OUT_F;

    cudaFuncSetAttribute(moe_gemm_kernel,
                         cudaFuncAttributeMaxDynamicSharedMemorySize, DYN_SMEM);

    xfrag_kernel<<<BATCH * IN_F / 4 / 256, 256>>>(x);
    wfrag_kernel<<<LEAVES * IN_F * OUT_F / 2 / 256, 256>>>(pw);   // FIXED grid
    gates_kernel<<<dim3(4, 256), 256>>>(x, gw, gb);
    leaf_kernel<<<64, 256>>>(lp);
    moe_gemm_kernel<<<dim3(128, 64), 256, DYN_SMEM>>>(pb, out);
}

// round 7
// speedup vs baseline: 2.1686x; 1.0267x over previous
#include <cuda_runtime.h>
#include <cstdint>

#define BATCH   16384
#define IN_F    512
#define OUT_F   64
#define LEAVES  256
#define GATES   255
#define PI_F    3.14159265358979323846f

// Scratch (device globals; no allocation allowed)
__device__ float g_gates[GATES * BATCH];              // sigmoid gates [gate][batch]
__device__ float g_xF [BATCH * IN_F];                 // frag-order tf32 X (hi)
__device__ float g_xLo[BATCH * IN_F];                 // frag-order tf32 X (lo residual)
__device__ float g_wF [LEAVES * IN_F * OUT_F];        // frag-order tf32 W
__device__ float g_gwHi[IN_F * 256];                  // frag-order tf32 GW hi (n padded to 256)
__device__ float g_gwLo[IN_F * 256];                  // frag-order tf32 GW lo

// ---------------------------------------------------------------------------
// helpers
// ---------------------------------------------------------------------------
__device__ __forceinline__ float to_tf32(float x) {
    uint32_t u;
    asm("cvt.rna.tf32.f32 %0, %1;" : "=r"(u) : "f"(x));
    return __uint_as_float(u);
}
__device__ __forceinline__ float sigmoid_f(float z) {
    return __fdividef(1.0f, 1.0f + __expf(-z));
}
__device__ __forceinline__ float tanhpi_f(float z) {
    float e = __expf(2.0f * z);
    return (1.0f - __fdividef(2.0f, e + 1.0f)) * PI_F;
}
__device__ __forceinline__ uint32_t smem_u32(const void* p) {
    uint32_t a;
    asm("{ .reg .u64 t; cvta.to.shared.u64 t, %1; cvt.u32.u64 %0, t; }"
        : "=r"(a) : "l"(p));
    return a;
}
__device__ __forceinline__ void cp16(uint32_t dst, const float* src) {
    asm volatile("cp.async.cg.shared.global [%0], [%1], 16;"
                 :: "r"(dst), "l"(__cvta_generic_to_global(src)));
}
__device__ __forceinline__ void mma_tf32(float c[4], const float4 a, float b0, float b1) {
    asm volatile(
        "mma.sync.aligned.m16n8k8.row.col.f32.tf32.tf32.f32 "
        "{%0,%1,%2,%3}, {%4,%5,%6,%7}, {%8,%9}, {%0,%1,%2,%3};\n"
        : "+f"(c[0]), "+f"(c[1]), "+f"(c[2]), "+f"(c[3])
        : "r"(__float_as_uint(a.x)), "r"(__float_as_uint(a.y)),
          "r"(__float_as_uint(a.z)), "r"(__float_as_uint(a.w)),
          "r"(__float_as_uint(b0)), "r"(__float_as_uint(b1)));
}

// ---------------------------------------------------------------------------
// Pre-pass: X -> fragment order, hi (tf32 rna) and lo (residual, tf32 rna)
// g_xF[((mb16*64 + kb8)*32 + lane)*4 + r]
// frag = {X[R+g][K+t], X[R+g+8][K+t], X[R+g][K+t+4], X[R+g+8][K+t+4]}
// ---------------------------------------------------------------------------
__global__ __launch_bounds__(256) void xfrag_kernel(const float* __restrict__ x) {
    const int tg = blockIdx.x * 256 + threadIdx.x;   // float4 index
    const int lane = tg & 31;
    const int kb8  = (tg >> 5) & 63;
    const int mb16 = tg >> 11;
    const int g = lane >> 2, t = lane & 3;
    const int R = mb16 * 16, K = kb8 * 8;
    float4 o;
    o.x = x[(size_t)(R + g)     * IN_F + K + t];
    o.y = x[(size_t)(R + g + 8) * IN_F + K + t];
    o.z = x[(size_t)(R + g)     * IN_F + K + t + 4];
    o.w = x[(size_t)(R + g + 8) * IN_F + K + t + 4];
    float4 hi, lo;
    hi.x = to_tf32(o.x); lo.x = to_tf32(o.x - hi.x);
    hi.y = to_tf32(o.y); lo.y = to_tf32(o.y - hi.y);
    hi.z = to_tf32(o.z); lo.z = to_tf32(o.z - hi.z);
    hi.w = to_tf32(o.w); lo.w = to_tf32(o.w - hi.w);
    reinterpret_cast<float4*>(g_xF)[tg]  = hi;
    reinterpret_cast<float4*>(g_xLo)[tg] = lo;
}

// ---------------------------------------------------------------------------
// Pre-pass: W -> fragment order (tf32 rna)
// g_wF[(((leaf*8 + n8)*64 + kb8)*32 + lane)*2 + r]
// frag = {W[l][K+t][N8+g], W[l][K+t+4][N8+g]}
// ---------------------------------------------------------------------------
__global__ __launch_bounds__(256) void wfrag_kernel(const float* __restrict__ pw) {
    const int tg = blockIdx.x * 256 + threadIdx.x;   // float2 index
    const int lane = tg & 31;
    const int kb8  = (tg >> 5) & 63;
    const int n8   = (tg >> 11) & 7;
    const int leaf = tg >> 14;
    const int g = lane >> 2, t = lane & 3;
    const int K = kb8 * 8, N8 = n8 * 8;
    float2 v;
    v.x = to_tf32(pw[((size_t)leaf * IN_F + K + t)     * OUT_F + N8 + g]);
    v.y = to_tf32(pw[((size_t)leaf * IN_F + K + t + 4) * OUT_F + N8 + g]);
    reinterpret_cast<float2*>(g_wF)[tg] = v;
}

// ---------------------------------------------------------------------------
// Pre-pass: GW -> fragment order hi/lo (tf32 rna); n padded to 256 with zeros
// g_gwHi/Lo float2 index = (n8*64 + kb8)*32 + lane; n8 in [0,32)
// frag = {GW[K+t][N8+g], GW[K+t+4][N8+g]}
// ---------------------------------------------------------------------------
__global__ __launch_bounds__(256) void gwfrag_kernel(const float* __restrict__ gw) {
    const int tg = blockIdx.x * 256 + threadIdx.x;   // 0..65535
    const int lane = tg & 31;
    const int kb8  = (tg >> 5) & 63;
    const int n8   = tg >> 11;
    const int g = lane >> 2, t = lane & 3;
    const int K = kb8 * 8, N = n8 * 8 + g;
    float a = 0.0f, b = 0.0f;
    if (N < GATES) {
        a = gw[(size_t)(K + t)     * GATES + N];
        b = gw[(size_t)(K + t + 4) * GATES + N];
    }
    float2 hi, lo;
    hi.x = to_tf32(a); lo.x = to_tf32(a - hi.x);
    hi.y = to_tf32(b); lo.y = to_tf32(b - hi.y);
    reinterpret_cast<float2*>(g_gwHi)[tg] = hi;
    reinterpret_cast<float2*>(g_gwLo)[tg] = lo;
}

// ---------------------------------------------------------------------------
// Gate GEMM via split-tf32 mma: Z = Xhi@Whi + Xhi@Wlo + Xlo@Whi  (~fp32 exact)
// CTA 256 thr; tile M=128 x N=128; K loop BK=32, 3-stage cp.async (192KB).
// Warp grid 2(M) x 4(N); warp tile 64x32.
// Stage: [Xhi 16K][Xlo 16K][Whi 16K][Wlo 16K] = 64KB.
// Stores sigmoid(z+gb) transposed into g_gates[n][b].
// ---------------------------------------------------------------------------
#define GST_WORDS  16384
#define GST_BYTES  65536
#define G_DYN_SMEM (3 * GST_BYTES)

__device__ __forceinline__ void gates_load_stage(uint32_t sm_b, int slot, int it,
                                                 int bm, int bn, int tid) {
    const uint32_t sb = sm_b + slot * GST_BYTES;
#pragma unroll
    for (int i = 0; i < 4; ++i) {          // X chunks (1024 per component)
        const int c = tid + i * 256;
        const int mb16l = c >> 7, kb8l = (c >> 5) & 3, lane = c & 31;
        const size_t fi = (((size_t)(bm * 8 + mb16l) * 64) + it * 4 + kb8l) * 32 + lane;
        cp16(sb + c * 16,          g_xF  + fi * 4);
        cp16(sb + 16384 + c * 16,  g_xLo + fi * 4);
    }
#pragma unroll
    for (int i = 0; i < 4; ++i) {          // W chunks (1024 per component)
        const int c = tid + i * 256;
        const int n8l = c >> 6, kb8l = (c >> 4) & 3, p = c & 15;
        const size_t fo = ((((size_t)(bn * 16 + n8l) * 64) + it * 4 + kb8l) * 32 + 2 * p) * 2;
        cp16(sb + 32768 + c * 16,  g_gwHi + fo);
        cp16(sb + 49152 + c * 16,  g_gwLo + fo);
    }
    asm volatile("cp.async.commit_group;" ::: "memory");
}

__global__ __launch_bounds__(256, 1) void gates_mma_kernel(
    const float* __restrict__ gb)
{
    extern __shared__ float sm[];
    const uint32_t sm_b = smem_u32(sm);

    const int tid = threadIdx.x;
    const int bm = blockIdx.x;      // 0..127
    const int bn = blockIdx.y;      // 0..1
    const int warp = tid >> 5, lane = tid & 31;
    const int wm = warp & 1, wn = warp >> 1;
    const int g = lane >> 2, t = lane & 3;

    float acc[4][4][4];
#pragma unroll
    for (int mi = 0; mi < 4; ++mi)
#pragma unroll
        for (int ni = 0; ni < 4; ++ni)
#pragma unroll
            for (int r = 0; r < 4; ++r) acc[mi][ni][r] = 0.0f;

    gates_load_stage(sm_b, 0, 0, bm, bn, tid);
    gates_load_stage(sm_b, 1, 1, bm, bn, tid);

#pragma unroll 1
    for (int it = 0; it < 16; ++it) {
        const int slot = it % 3;
        asm volatile("cp.async.wait_group 1;" ::: "memory");
        __syncthreads();
        if (it + 2 < 16)
            gates_load_stage(sm_b, (it + 2) % 3, it + 2, bm, bn, tid);
        else
            asm volatile("cp.async.commit_group;" ::: "memory");

        const float* Xhi = sm + slot * GST_WORDS;
        const float* Xlo = Xhi + 4096;
        const float* Whi = Xhi + 8192;
        const float* Wlo = Xhi + 12288;

#pragma unroll
        for (int s = 0; s < 4; ++s) {
            float4 ahi[4], alo[4];
#pragma unroll
            for (int mi = 0; mi < 4; ++mi) {
                const int fi = ((wm * 4 + mi) * 4 + s) * 32 + lane;
                ahi[mi] = reinterpret_cast<const float4*>(Xhi)[fi];
                alo[mi] = reinterpret_cast<const float4*>(Xlo)[fi];
            }
#pragma unroll
            for (int ni = 0; ni < 4; ++ni) {
                const int fo = ((wn * 4 + ni) * 4 + s) * 32 + lane;
                float2 bhi = reinterpret_cast<const float2*>(Whi)[fo];
                float2 blo = reinterpret_cast<const float2*>(Wlo)[fo];
#pragma unroll
                for (int mi = 0; mi < 4; ++mi) {
                    mma_tf32(acc[mi][ni], ahi[mi], bhi.x, bhi.y);
                    mma_tf32(acc[mi][ni], ahi[mi], blo.x, blo.y);
                    mma_tf32(acc[mi][ni], alo[mi], bhi.x, bhi.y);
                }
            }
        }
    }

    // Epilogue: sigmoid(z+gb) -> g_gates[n][b] (transposed scatter)
#pragma unroll
    for (int ni = 0; ni < 4; ++ni) {
        const int n0 = bn * 128 + wn * 32 + ni * 8 + 2 * t;
        const float gb0 = (n0 < GATES)     ? gb[n0]     : 0.0f;
        const float gb1 = (n0 + 1 < GATES) ? gb[n0 + 1] : 0.0f;
#pragma unroll
        for (int mi = 0; mi < 4; ++mi) {
            const int b0 = bm * 128 + wm * 64 + mi * 16 + g;
            if (n0 < GATES) {
                g_gates[(size_t)n0 * BATCH + b0]     = sigmoid_f(acc[mi][ni][0] + gb0);
                g_gates[(size_t)n0 * BATCH + b0 + 8] = sigmoid_f(acc[mi][ni][2] + gb0);
            }
            if (n0 + 1 < GATES) {
                g_gates[(size_t)(n0 + 1) * BATCH + b0]     = sigmoid_f(acc[mi][ni][1] + gb1);
                g_gates[(size_t)(n0 + 1) * BATCH + b0 + 8] = sigmoid_f(acc[mi][ni][3] + gb1);
            }
        }
    }
}

// ---------------------------------------------------------------------------
// Leaf probabilities
// ---------------------------------------------------------------------------
__global__ __launch_bounds__(128) void leaf_kernel(float* __restrict__ lp)
{
    const int b = blockIdx.x * 128 + threadIdx.x;

    float dens[32];
    dens[0] = 1.0f;
#pragma unroll
    for (int d = 0; d < 5; ++d) {
        const int width = 1 << d;
        const int base = width - 1;
#pragma unroll
        for (int i = width - 1; i >= 0; --i) {
            float g = g_gates[(size_t)(base + i) * BATCH + b];
            float v = dens[i];
            float vg = v * g;
            dens[2 * i]     = vg;
            dens[2 * i + 1] = v - vg;
        }
    }
#pragma unroll
    for (int i = 0; i < 32; ++i) {
        float p  = dens[i];
        float g5 = g_gates[(size_t)(31 + i) * BATCH + b];
        float a0 = p * g5, a1 = p - a0;
        float g6a = g_gates[(size_t)(63 + 2 * i) * BATCH + b];
        float g6b = g_gates[(size_t)(63 + 2 * i + 1) * BATCH + b];
        float c0 = a0 * g6a, c1 = a0 - c0;
        float c2 = a1 * g6b, c3 = a1 - c2;
        float q[4] = {c0, c1, c2, c3};
#pragma unroll
        for (int j = 0; j < 4; ++j) {
            float g7 = g_gates[(size_t)(127 + 4 * i + j) * BATCH + b];
            float e0 = q[j] * g7;
            float e1 = q[j] - e0;
            int leaf = 8 * i + 2 * j;
            lp[(size_t)leaf * BATCH + b]       = e0;
            lp[(size_t)(leaf + 1) * BATCH + b] = e1;
        }
    }
}

// ---------------------------------------------------------------------------
// Main GEMM: tf32 mma.sync, fragment-order smem, BK=32/stage, 3-stage cp.async.
// CTA: 256 threads (8 warps). Tile M=128 x N=256 (4 leaves).
// Warp grid 2(M) x 4(N); warp tile 64x64.
// Stage: X 16KB + W 32KB = 48KB; 3 stages = 144KB.
// ---------------------------------------------------------------------------
#define STAGE_BYTES 49152
#define STAGE_WORDS 12288
#define XW_WORDS    4096              // X words per stage
#define DYN_SMEM    (3 * STAGE_BYTES)

__device__ __forceinline__ void moe_load_stage(uint32_t sm_b, int slot, int it,
                                               int bm, int lg, int tid) {
    const uint32_t sb = sm_b + slot * STAGE_BYTES;
    // X: 1024 chunks; c = (mb16l*4 + kb8l)*32 + lane
#pragma unroll
    for (int i = 0; i < 4; ++i) {
        const int c = tid + i * 256;
        const int mb16l = c >> 7, kb8l = (c >> 5) & 3, lane = c & 31;
        cp16(sb + c * 16,
             g_xF + ((((size_t)(bm * 8 + mb16l) * 64) + it * 4 + kb8l) * 32 + lane) * 4);
    }
    // W: 2048 chunks; c = ((leafl*8+n8)*4 + kb8l)*16 + p
#pragma unroll
    for (int i = 0; i < 8; ++i) {
        const int c = tid + i * 256;
        const int leafl = c >> 9;
        const int n8    = (c >> 6) & 7;
        const int kb8l  = (c >> 4) & 3;
        const int p     = c & 15;
        cp16(sb + 16384 + c * 16,
             g_wF + (((((size_t)(lg * 4 + leafl) * 8 + n8) * 64) + it * 4 + kb8l) * 32
                     + 2 * p) * 2);
    }
    asm volatile("cp.async.commit_group;" ::: "memory");
}

__global__ __launch_bounds__(256, 1) void moe_gemm_kernel(
    const float* __restrict__ pb, float* __restrict__ out)
{
    extern __shared__ float sm[];
    const uint32_t sm_b = smem_u32(sm);

    const int tid  = threadIdx.x;
    const int bm   = blockIdx.x;    // 0..127 (M tiles of 128)
    const int lg   = blockIdx.y;    // 0..63  (leaf groups of 4)
    const int warp = tid >> 5, lane = tid & 31;
    const int wm = warp & 1, wn = warp >> 1;
    const int g = lane >> 2, t = lane & 3;

    float acc[4][8][4];
#pragma unroll
    for (int mi = 0; mi < 4; ++mi)
#pragma unroll
        for (int ni = 0; ni < 8; ++ni)
#pragma unroll
            for (int r = 0; r < 4; ++r) acc[mi][ni][r] = 0.0f;

    moe_load_stage(sm_b, 0, 0, bm, lg, tid);
    moe_load_stage(sm_b, 1, 1, bm, lg, tid);

#pragma unroll 1
    for (int it = 0; it < 16; ++it) {
        const int slot = it % 3;
        asm volatile("cp.async.wait_group 1;" ::: "memory");
        __syncthreads();
        if (it + 2 < 16)
            moe_load_stage(sm_b, (it + 2) % 3, it + 2, bm, lg, tid);
        else
            asm volatile("cp.async.commit_group;" ::: "memory");

        const float* Xs = sm + slot * STAGE_WORDS;
        const float* Ws = Xs + XW_WORDS;

#pragma unroll
        for (int s = 0; s < 4; ++s) {
            float4 a[4];
#pragma unroll
            for (int mi = 0; mi < 4; ++mi)
                a[mi] = reinterpret_cast<const float4*>(Xs)[
                    ((wm * 4 + mi) * 4 + s) * 32 + lane];
#pragma unroll
            for (int ni = 0; ni < 8; ++ni) {
                float2 b = reinterpret_cast<const float2*>(Ws)[
                    ((wn * 8 + ni) * 4 + s) * 32 + lane];
#pragma unroll
                for (int mi = 0; mi < 4; ++mi)
                    mma_tf32(acc[mi][ni], a[mi], b.x, b.y);
            }
        }
    }

    // Epilogue: +pb, activation, store (leaf = lg*4 + wn; warp owns full leaf)
    const int leaf = lg * 4 + wn;
    float pb0[8], pb1[8];
#pragma unroll
    for (int ni = 0; ni < 8; ++ni) {
        const int o = ni * 8 + 2 * t;
        pb0[ni] = pb[leaf * 64 + o];
        pb1[ni] = pb[leaf * 64 + o + 1];
    }

#pragma unroll
    for (int mi = 0; mi < 4; ++mi) {
        const int row0 = bm * 128 + wm * 64 + mi * 16 + g;
#pragma unroll
        for (int ni = 0; ni < 8; ++ni) {
            const int o = ni * 8 + 2 * t;
            const bool is_tanh = (ni < 4);
            float v0 = acc[mi][ni][0] + pb0[ni];
            float v1 = acc[mi][ni][1] + pb1[ni];
            float v2 = acc[mi][ni][2] + pb0[ni];
            float v3 = acc[mi][ni][3] + pb1[ni];
            if (is_tanh) {
                v0 = tanhpi_f(v0); v1 = tanhpi_f(v1);
                v2 = tanhpi_f(v2); v3 = tanhpi_f(v3);
            } else {
                v0 = sigmoid_f(v0); v1 = sigmoid_f(v1);
                v2 = sigmoid_f(v2); v3 = sigmoid_f(v3);
            }
            *reinterpret_cast<float2*>(
                out + ((size_t)leaf * BATCH + row0) * OUT_F + o) = make_float2(v0, v1);
            *reinterpret_cast<float2*>(
                out + ((size_t)leaf * BATCH + row0 + 8) * OUT_F + o) = make_float2(v2, v3);
        }
    }
}

// ---------------------------------------------------------------------------
extern "C" void kernel_launch(void* const* d_in, const int* in_sizes, int n_in,
                              void* d_out, int out_size)
{
    const float* x  = (const float*)d_in[0];
    const float* gw = (const float*)d_in[1];
    const float* gb = (const float*)d_in[2];
    const float* pw = (const float*)d_in[3];
    const float* pb = (const float*)d_in[4];

    float* out = (float*)d_out;
    float* lp  = out + (size_t)LEAVES * BATCH * OUT_F;

    cudaFuncSetAttribute(moe_gemm_kernel,
                         cudaFuncAttributeMaxDynamicSharedMemorySize, DYN_SMEM);
    cudaFuncSetAttribute(gates_mma_kernel,
                         cudaFuncAttributeMaxDynamicSharedMemorySize, G_DYN_SMEM);

    xfrag_kernel<<<BATCH * IN_F / 4 / 256, 256>>>(x);
    wfrag_kernel<<<LEAVES * IN_F * OUT_F / 2 / 256, 256>>>(pw);
    gwfrag_kernel<<<IN_F * 256 / 2 / 256, 256>>>(gw);
    gates_mma_kernel<<<dim3(128, 2), 256, G_DYN_SMEM>>>(gb);
    leaf_kernel<<<128, 128>>>(lp);
    moe_gemm_kernel<<<dim3(128, 64), 256, DYN_SMEM>>>(pb, out);
}